// round 9
// baseline (speedup 1.0000x reference)
#include <cuda_runtime.h>
#include <cuda_fp16.h>
#include <cstdint>
#include <math.h>

#define DEV_INLINE __device__ __forceinline__

#define BB 8
#define SS 2048
#define DD 1024
#define MTOT (BB * SS)   // 16384

// ---------------------------------------------------------------------------
// Scratch (__device__ globals; allocation-free rule). 16B aligned for cp.async.
// ---------------------------------------------------------------------------
__device__ __align__(16) __half g_x1h[(size_t)MTOT * DD];
__device__ __align__(16) __half g_x2h[(size_t)MTOT * DD];
__device__ __align__(16) __half g_wqT[DD * DD];
__device__ __align__(16) __half g_wkT[DD * DD];
__device__ __align__(16) __half g_wvT[DD * DD];
__device__ __align__(16) __half g_woT[DD * DD];
__device__ __align__(16) __half g_Q [(size_t)MTOT * DD];
__device__ __align__(16) __half g_K [(size_t)MTOT * DD];
__device__ __align__(16) __half g_Vt[(size_t)DD * MTOT];       // [D, B*S]
__device__ __align__(16) __half g_P [(size_t)BB * SS * SS];
__device__ __align__(16) __half g_Y [(size_t)MTOT * DD];

// ---------------------------------------------------------------------------
// Helpers
// ---------------------------------------------------------------------------
DEV_INLINE uint32_t smem_u32(const void* p) {
    uint32_t a;
    asm("{ .reg .u64 t; cvta.to.shared.u64 t, %1; cvt.u32.u64 %0, t; }" : "=r"(a) : "l"(p));
    return a;
}
DEV_INLINE void cp16(uint32_t s, const void* g) {
    asm volatile("cp.async.cg.shared.global [%0], [%1], 16;" :: "r"(s), "l"(g));
}
DEV_INLINE void cp_commit() { asm volatile("cp.async.commit_group;" ::: "memory"); }
template <int N> DEV_INLINE void cp_wait() {
    asm volatile("cp.async.wait_group %0;" :: "n"(N) : "memory");
}

#define LDSM4(R0, R1, R2, R3, addr)                                           \
    asm volatile("ldmatrix.sync.aligned.m8n8.x4.shared.b16 {%0,%1,%2,%3}, [%4];" \
                 : "=r"(R0), "=r"(R1), "=r"(R2), "=r"(R3) : "r"(addr))

DEV_INLINE void mma_f16(float* d, const uint32_t* a, const uint32_t* b) {
    asm volatile(
        "mma.sync.aligned.m16n8k16.row.col.f32.f16.f16.f32 "
        "{%0,%1,%2,%3}, {%4,%5,%6,%7}, {%8,%9}, {%0,%1,%2,%3};\n"
        : "+f"(d[0]), "+f"(d[1]), "+f"(d[2]), "+f"(d[3])
        : "r"(a[0]), "r"(a[1]), "r"(a[2]), "r"(a[3]),
          "r"(b[0]), "r"(b[1]));
}

// swizzled byte offset of 16B chunk (row, kc) in a tile with 32B rows
DEV_INLINE uint32_t swz(int row, int kc) {
    return (uint32_t)(row * 32 + ((kc ^ ((row >> 2) & 1)) << 4));
}

// ---------------------------------------------------------------------------
// FP16 tensor-core GEMM:  C[M,N] = alpha * A[M,K] @ B[N,K]^T  (K-major fp16)
// CTA tile 128x128, 4 warps (2 M x 2 N), warp tile 64x64, k-step 16.
// 6-stage cp.async pipeline (48KB) -> 2 CTAs/SM; fragments double-buffered
// (LDSM for kt+1 issued before HMMAs of kt; no dependency => latency hidden).
// MERGE: blockIdx.z selects operand set 0/1. OUTH: store __half; else fp32.
// Grid: (N/128, M/128, z), block 128.
// ---------------------------------------------------------------------------
#define NSTG 6
#define A_BYTES (128 * 32)                  // 4 KB
#define B_BYTES (128 * 32)                  // 4 KB
#define STG_BYTES (A_BYTES + B_BYTES)       // 8 KB
#define SMEM_DYN (NSTG * STG_BYTES)         // 48 KB

template <bool MERGE, bool OUTH, bool RELU>
__global__ void __launch_bounds__(128, 2)
gemm_h(const __half* __restrict__ A0, const __half* __restrict__ B0, void* __restrict__ C0,
       const __half* __restrict__ A1, const __half* __restrict__ B1, void* __restrict__ C1,
       int lda, int ldb, int ldc, int nk, float alpha0, float alpha1,
       size_t sAz, size_t sBz, size_t sCz)
{
    const bool sel = MERGE && (blockIdx.z & 1);
    const __half* A = sel ? A1 : A0;
    const __half* B = sel ? B1 : B0;
    void* Cv        = sel ? C1 : C0;
    const float alpha = sel ? alpha1 : alpha0;
    const size_t zoff = MERGE ? 0 : (size_t)blockIdx.z;
    A += zoff * sAz;
    B += zoff * sBz;

    const int bm = blockIdx.y, bn = blockIdx.x;
    const int tid  = threadIdx.x;
    const int warp = tid >> 5;
    const int lane = tid & 31;
    const int wm   = warp >> 1;             // 0..1 : 64-row band
    const int wn   = warp & 1;              // 0..1 : 64-col band
    const int grp  = lane >> 2;             // 0..7
    const int tig  = lane & 3;              // 0..3

    extern __shared__ char dsm[];
    const uint32_t sb = smem_u32(dsm);

    // per-lane ldmatrix.x4 offsets (verified mapping, 64x64 warp tile)
    const int lT = lane >> 3, lr = lane & 7;
    uint32_t offA[4], offB[4];
    {
        const int am  = wm * 64 + (lT & 1) * 8 + lr;     // + mt*16
        const int akc = lT >> 1;
#pragma unroll
        for (int mt = 0; mt < 4; mt++) offA[mt] = swz(am + mt * 16, akc);
        const int bn0 = wn * 64 + ((lT >> 1) << 3) + lr; // + j*16
        const int bkc = lT & 1;
#pragma unroll
        for (int j = 0; j < 4; j++) offB[j] = (uint32_t)A_BYTES + swz(bn0 + j * 16, bkc);
    }

    const __half* Abase = A + (size_t)(bm * 128) * lda;
    const __half* Bbase = B + (size_t)(bn * 128) * ldb;

    auto load_stage = [&](int s, int kt) {
        const uint32_t st = sb + (uint32_t)(s * STG_BYTES);
        const int k0 = kt * 16;
#pragma unroll
        for (int i = 0; i < 2; i++) {        // A: 128 rows x 2 chunks = 256
            const int lin = tid + i * 128;
            const int row = lin >> 1, kc = lin & 1;
            cp16(st + swz(row, kc), Abase + (size_t)row * lda + k0 + kc * 8);
        }
#pragma unroll
        for (int i = 0; i < 2; i++) {        // B: 128 rows x 2 chunks = 256
            const int lin = tid + i * 128;
            const int row = lin >> 1, kc = lin & 1;
            cp16(st + A_BYTES + swz(row, kc), Bbase + (size_t)row * ldb + k0 + kc * 8);
        }
        cp_commit();
    };

    // prologue: stages 0..4 in flight
#pragma unroll
    for (int s = 0; s < 5; s++) load_stage(s, s);

    uint32_t a[2][4][4], b[2][8][2];
    float acc[4][8][4] = {};

    auto ldsm_stage = [&](int buf, int slot) {
        const uint32_t st = sb + (uint32_t)(slot * STG_BYTES);
#pragma unroll
        for (int mt = 0; mt < 4; mt++)
            LDSM4(a[buf][mt][0], a[buf][mt][1], a[buf][mt][2], a[buf][mt][3], st + offA[mt]);
#pragma unroll
        for (int j = 0; j < 4; j++) {
            uint32_t r0, r1, r2, r3;
            LDSM4(r0, r1, r2, r3, st + offB[j]);
            b[buf][2 * j][0] = r0; b[buf][2 * j][1] = r1;
            b[buf][2 * j + 1][0] = r2; b[buf][2 * j + 1][1] = r3;
        }
    };

    // stage 0 ready -> frags buf0
    cp_wait<4>();
    __syncthreads();
    ldsm_stage(0, 0);

    int sl = 5;                              // next slot to fill
    int rs = 1;                              // slot of stage kt+1
    for (int kt = 0; kt < nk; kt++) {
        const int cur = kt & 1;

        if (kt + 1 < nk) {
            const int rem = nk - 2 - kt;     // groups issued beyond kt+1 (max 3)
            if      (rem >= 3) cp_wait<3>();
            else if (rem == 2) cp_wait<2>();
            else if (rem == 1) cp_wait<1>();
            else               cp_wait<0>();
            __syncthreads();
            ldsm_stage(cur ^ 1, rs);
            if (++rs == NSTG) rs = 0;
            if (kt + 5 < nk) {
                load_stage(sl, kt + 5);
                if (++sl == NSTG) sl = 0;
            }
        }

        // 32 HMMA on current buffer (no dependency on the LDSMs just issued)
#pragma unroll
        for (int mt = 0; mt < 4; mt++)
#pragma unroll
            for (int nt = 0; nt < 8; nt++)
                mma_f16(acc[mt][nt], a[cur][mt], b[cur][nt]);
    }

    // ---- epilogue ----
    const int r0 = bm * 128 + wm * 64;
    const int c0 = bn * 128 + wn * 64;
#pragma unroll
    for (int mt = 0; mt < 4; mt++) {
#pragma unroll
        for (int nt = 0; nt < 8; nt++) {
            const int r = r0 + mt * 16 + grp;
            const int c = c0 + nt * 8 + tig * 2;
            float v0 = acc[mt][nt][0] * alpha;
            float v1 = acc[mt][nt][1] * alpha;
            float v2 = acc[mt][nt][2] * alpha;
            float v3 = acc[mt][nt][3] * alpha;
            if (RELU) {
                v0 = fmaxf(v0, 0.f); v1 = fmaxf(v1, 0.f);
                v2 = fmaxf(v2, 0.f); v3 = fmaxf(v3, 0.f);
            }
            if (OUTH) {
                __half* C = (__half*)Cv + zoff * sCz;
                *(__half2*)(C + (size_t)r * ldc + c)       = __floats2half2_rn(v0, v1);
                *(__half2*)(C + (size_t)(r + 8) * ldc + c) = __floats2half2_rn(v2, v3);
            } else {
                float* C = (float*)Cv + zoff * sCz;
                *(float2*)(C + (size_t)r * ldc + c)       = make_float2(v0, v1);
                *(float2*)(C + (size_t)(r + 8) * ldc + c) = make_float2(v2, v3);
            }
        }
    }
}

// ---------------------------------------------------------------------------
// Prep: fp32 -> fp16 for x1 and x2 in one launch (blockIdx.y selects)
// ---------------------------------------------------------------------------
__global__ void __launch_bounds__(256)
f2h_two(const float4* __restrict__ s1, __half2* __restrict__ d1,
        const float4* __restrict__ s2, __half2* __restrict__ d2, int n4)
{
    const int i = blockIdx.x * 256 + threadIdx.x;
    if (i >= n4) return;
    const float4* s = blockIdx.y ? s2 : s1;
    __half2*      d = blockIdx.y ? d2 : d1;
    const float4 v = s[i];
    d[2 * i]     = __floats2half2_rn(v.x, v.y);
    d[2 * i + 1] = __floats2half2_rn(v.z, v.w);
}

// 4 weight transposes (to K-major) + fp16 convert in one launch (blockIdx.z)
__global__ void __launch_bounds__(256)
transpose_h4(const float* __restrict__ w0, const float* __restrict__ w1,
             const float* __restrict__ w2, const float* __restrict__ w3,
             __half* __restrict__ t0, __half* __restrict__ t1,
             __half* __restrict__ t2, __half* __restrict__ t3)
{
    const float* w = (blockIdx.z == 0) ? w0 : (blockIdx.z == 1) ? w1
                   : (blockIdx.z == 2) ? w2 : w3;
    __half* wt     = (blockIdx.z == 0) ? t0 : (blockIdx.z == 1) ? t1
                   : (blockIdx.z == 2) ? t2 : t3;

    __shared__ float t[32][33];
    const int bx = blockIdx.x * 32, by = blockIdx.y * 32;
    const int x = threadIdx.x & 31, y4 = threadIdx.x >> 5;
#pragma unroll
    for (int i = 0; i < 32; i += 8)
        t[y4 + i][x] = w[(size_t)(by + y4 + i) * DD + bx + x];
    __syncthreads();
#pragma unroll
    for (int i = 0; i < 32; i += 8)
        wt[(size_t)(bx + y4 + i) * DD + by + x] = __float2half_rn(t[x][y4 + i]);
}

// ---------------------------------------------------------------------------
// Row softmax with additive mask on fp16 P (compute fp32, store fp16)
// ---------------------------------------------------------------------------
__global__ void __launch_bounds__(256)
softmax_mask(__half* __restrict__ P, const int* __restrict__ mask)
{
    const int row = blockIdx.x;
    const int b   = row >> 11;
    __half* p = P + (size_t)row * SS;
    const int* mrow = mask + (size_t)b * SS;

    const int tid = threadIdx.x, lane = tid & 31, warp = tid >> 5;
    __shared__ float red[8];

    float v[8];
    float mx = -INFINITY;
#pragma unroll
    for (int i = 0; i < 8; i++) {
        const int j = tid + i * 256;
        float x = __half2float(p[j]);
        if (mrow[j]) x -= 1.0e9f;
        v[i] = x;
        mx = fmaxf(mx, x);
    }
#pragma unroll
    for (int o = 16; o; o >>= 1) mx = fmaxf(mx, __shfl_xor_sync(0xffffffffu, mx, o));
    if (lane == 0) red[warp] = mx;
    __syncthreads();
    mx = red[0];
#pragma unroll
    for (int w = 1; w < 8; w++) mx = fmaxf(mx, red[w]);

    float s = 0.f;
#pragma unroll
    for (int i = 0; i < 8; i++) {
        const float e = __expf(v[i] - mx);
        v[i] = e;
        s += e;
    }
    __syncthreads();
#pragma unroll
    for (int o = 16; o; o >>= 1) s += __shfl_xor_sync(0xffffffffu, s, o);
    if (lane == 0) red[warp] = s;
    __syncthreads();
    s = red[0];
#pragma unroll
    for (int w = 1; w < 8; w++) s += red[w];

    const float inv = 1.0f / s;
#pragma unroll
    for (int i = 0; i < 8; i++) p[tid + i * 256] = __float2half_rn(v[i] * inv);
}

// ---------------------------------------------------------------------------
// Launch
// ---------------------------------------------------------------------------
extern "C" void kernel_launch(void* const* d_in, const int* in_sizes, int n_in,
                              void* d_out, int out_size)
{
    (void)in_sizes; (void)n_in; (void)out_size;

    const float* x1      = (const float*)d_in[0];
    const float* x2      = (const float*)d_in[1];
    const int*   maskSeq = (const int*)  d_in[2];
    const float* wq      = (const float*)d_in[3];
    const float* wk      = (const float*)d_in[4];
    const float* wv      = (const float*)d_in[5];
    const float* wo      = (const float*)d_in[6];
    float* out = (float*)d_out;

    __half *x1h, *x2h, *wqT, *wkT, *wvT, *woT, *Q, *Kp, *Vt, *P, *Y;
    cudaGetSymbolAddress((void**)&x1h, g_x1h);
    cudaGetSymbolAddress((void**)&x2h, g_x2h);
    cudaGetSymbolAddress((void**)&wqT, g_wqT);
    cudaGetSymbolAddress((void**)&wkT, g_wkT);
    cudaGetSymbolAddress((void**)&wvT, g_wvT);
    cudaGetSymbolAddress((void**)&woT, g_woT);
    cudaGetSymbolAddress((void**)&Q,   g_Q);
    cudaGetSymbolAddress((void**)&Kp,  g_K);
    cudaGetSymbolAddress((void**)&Vt,  g_Vt);
    cudaGetSymbolAddress((void**)&P,   g_P);
    cudaGetSymbolAddress((void**)&Y,   g_Y);

    cudaFuncSetAttribute(gemm_h<true,  true,  false>, cudaFuncAttributeMaxDynamicSharedMemorySize, SMEM_DYN);
    cudaFuncSetAttribute(gemm_h<false, true,  false>, cudaFuncAttributeMaxDynamicSharedMemorySize, SMEM_DYN);
    cudaFuncSetAttribute(gemm_h<false, true,  true >, cudaFuncAttributeMaxDynamicSharedMemorySize, SMEM_DYN);
    cudaFuncSetAttribute(gemm_h<false, false, false>, cudaFuncAttributeMaxDynamicSharedMemorySize, SMEM_DYN);

    const float scale = 0.03125f;   // 1024^-0.5
    const int n4 = (MTOT * DD) / 4;

    // prep (2 launches)
    f2h_two<<<dim3(n4 / 256, 2), 256>>>((const float4*)x1, (__half2*)x1h,
                                        (const float4*)x2, (__half2*)x2h, n4);
    transpose_h4<<<dim3(32, 32, 4), 256>>>(wq, wk, wv, wo, wqT, wkT, wvT, woT);

    // merged: Q = h(scale * x1 @ wq)  and  K = h(x2 @ wk)
    gemm_h<true, true, false><<<dim3(DD / 128, MTOT / 128, 2), 128, SMEM_DYN>>>(
        x1h, wqT, Q, x2h, wkT, Kp, DD, DD, DD, DD / 16, scale, 1.f, 0, 0, 0);

    // Vt[e, s] = h( sum_d wvT[e,d] * x2h[s,d] )   (V transposed, K-major for PV)
    gemm_h<false, true, false><<<dim3(MTOT / 128, DD / 128, 1), 128, SMEM_DYN>>>(
        wvT, x2h, Vt, wvT, x2h, Vt, DD, DD, MTOT, DD / 16, 1.f, 1.f, 0, 0, 0);

    // P = Q @ K^T  (per batch)
    gemm_h<false, true, false><<<dim3(SS / 128, SS / 128, BB), 128, SMEM_DYN>>>(
        Q, Kp, P, Q, Kp, P, DD, DD, SS, DD / 16, 1.f, 1.f,
        (size_t)SS * DD, (size_t)SS * DD, (size_t)SS * SS);

    // mask + softmax (in place, fp16)
    softmax_mask<<<BB * SS, 256>>>(P, maskSeq);

    // Y = h(relu(P @ Vt^T))  (per batch; Vt batch slice via column offset)
    gemm_h<false, true, true><<<dim3(DD / 128, SS / 128, BB), 128, SMEM_DYN>>>(
        P, Vt, Y, P, Vt, Y, SS, MTOT, DD, SS / 16, 1.f, 1.f,
        (size_t)SS * SS, (size_t)SS, (size_t)SS * DD);

    // out = Y @ wo (fp32 out)
    gemm_h<false, false, false><<<dim3(DD / 128, MTOT / 128, 1), 128, SMEM_DYN>>>(
        Y, woT, out, Y, woT, out, DD, DD, DD, DD / 16, 1.f, 1.f, 0, 0, 0);
}

// round 10
// speedup vs baseline: 3.8657x; 3.8657x over previous
#include <cuda_runtime.h>
#include <cuda_fp16.h>
#include <cstdint>
#include <math.h>

#define DEV_INLINE __device__ __forceinline__

#define BB 8
#define SS 2048
#define DD 1024
#define MTOT (BB * SS)   // 16384

// ---------------------------------------------------------------------------
// Scratch (__device__ globals; allocation-free rule). 16B aligned for cp.async.
// ---------------------------------------------------------------------------
__device__ __align__(16) __half g_x1h[(size_t)MTOT * DD];
__device__ __align__(16) __half g_x2h[(size_t)MTOT * DD];
__device__ __align__(16) __half g_wqT[DD * DD];
__device__ __align__(16) __half g_wkT[DD * DD];
__device__ __align__(16) __half g_wvT[DD * DD];
__device__ __align__(16) __half g_woT[DD * DD];
__device__ __align__(16) __half g_Q [(size_t)MTOT * DD];
__device__ __align__(16) __half g_K [(size_t)MTOT * DD];
__device__ __align__(16) __half g_Vt[(size_t)DD * MTOT];       // [D, B*S]
__device__ __align__(16) __half g_P [(size_t)BB * SS * SS];
__device__ __align__(16) __half g_Y [(size_t)MTOT * DD];

// ---------------------------------------------------------------------------
// Helpers
// ---------------------------------------------------------------------------
DEV_INLINE uint32_t smem_u32(const void* p) {
    uint32_t a;
    asm("{ .reg .u64 t; cvta.to.shared.u64 t, %1; cvt.u32.u64 %0, t; }" : "=r"(a) : "l"(p));
    return a;
}
DEV_INLINE void cp16(uint32_t s, const void* g) {
    asm volatile("cp.async.cg.shared.global [%0], [%1], 16;" :: "r"(s), "l"(g));
}
DEV_INLINE void cp_commit() { asm volatile("cp.async.commit_group;" ::: "memory"); }
template <int N> DEV_INLINE void cp_wait() {
    asm volatile("cp.async.wait_group %0;" :: "n"(N) : "memory");
}

#define LDSM4(R0, R1, R2, R3, addr)                                           \
    asm volatile("ldmatrix.sync.aligned.m8n8.x4.shared.b16 {%0,%1,%2,%3}, [%4];" \
                 : "=r"(R0), "=r"(R1), "=r"(R2), "=r"(R3) : "r"(addr))

DEV_INLINE void mma_f16(float* d, const uint32_t* a, const uint32_t* b) {
    asm volatile(
        "mma.sync.aligned.m16n8k16.row.col.f32.f16.f16.f32 "
        "{%0,%1,%2,%3}, {%4,%5,%6,%7}, {%8,%9}, {%0,%1,%2,%3};\n"
        : "+f"(d[0]), "+f"(d[1]), "+f"(d[2]), "+f"(d[3])
        : "r"(a[0]), "r"(a[1]), "r"(a[2]), "r"(a[3]),
          "r"(b[0]), "r"(b[1]));
}

// swizzled byte offset of 16B chunk (row, kc) in a tile with 32B rows
DEV_INLINE uint32_t swz(int row, int kc) {
    return (uint32_t)(row * 32 + ((kc ^ ((row >> 2) & 1)) << 4));
}

// ---------------------------------------------------------------------------
// FP16 tensor-core GEMM:  C[M,N] = alpha * A[M,K] @ B[N,K]^T  (K-major fp16)
// CTA tile 128x128, 4 warps (2 M x 2 N), warp tile 64x64 (best LDSM
// bytes/FLOP), SINGLE-buffered fragments (spill-free: ~182 regs, Round-6
// verified body), 6-stage cp.async pipeline (48KB) -> 2 CTAs/SM so the two
// independent pipelines cover each other's barrier/LDSM latency.
// MERGE: blockIdx.z selects operand set 0/1. OUTH: store __half; else fp32.
// Grid: (N/128, M/128, z), block 128.
// ---------------------------------------------------------------------------
#define NSTG 6
#define A_BYTES (128 * 32)                  // 4 KB
#define B_BYTES (128 * 32)                  // 4 KB
#define STG_BYTES (A_BYTES + B_BYTES)       // 8 KB
#define SMEM_DYN (NSTG * STG_BYTES)         // 48 KB

template <bool MERGE, bool OUTH, bool RELU>
__global__ void __launch_bounds__(128, 2)
gemm_h(const __half* __restrict__ A0, const __half* __restrict__ B0, void* __restrict__ C0,
       const __half* __restrict__ A1, const __half* __restrict__ B1, void* __restrict__ C1,
       int lda, int ldb, int ldc, int nk, float alpha0, float alpha1,
       size_t sAz, size_t sBz, size_t sCz)
{
    const bool sel = MERGE && (blockIdx.z & 1);
    const __half* A = sel ? A1 : A0;
    const __half* B = sel ? B1 : B0;
    void* Cv        = sel ? C1 : C0;
    const float alpha = sel ? alpha1 : alpha0;
    const size_t zoff = MERGE ? 0 : (size_t)blockIdx.z;
    A += zoff * sAz;
    B += zoff * sBz;

    const int bm = blockIdx.y, bn = blockIdx.x;
    const int tid  = threadIdx.x;
    const int warp = tid >> 5;
    const int lane = tid & 31;
    const int wm   = warp >> 1;             // 0..1 : 64-row band
    const int wn   = warp & 1;              // 0..1 : 64-col band
    const int grp  = lane >> 2;             // 0..7
    const int tig  = lane & 3;              // 0..3

    extern __shared__ char dsm[];
    const uint32_t sb = smem_u32(dsm);

    // per-lane ldmatrix.x4 offsets (verified mapping, 64x64 warp tile)
    const int lT = lane >> 3, lr = lane & 7;
    uint32_t offA[4], offB[4];
    {
        const int am  = wm * 64 + (lT & 1) * 8 + lr;     // + mt*16
        const int akc = lT >> 1;
#pragma unroll
        for (int mt = 0; mt < 4; mt++) offA[mt] = swz(am + mt * 16, akc);
        const int bn0 = wn * 64 + ((lT >> 1) << 3) + lr; // + j*16
        const int bkc = lT & 1;
#pragma unroll
        for (int j = 0; j < 4; j++) offB[j] = (uint32_t)A_BYTES + swz(bn0 + j * 16, bkc);
    }

    const __half* Abase = A + (size_t)(bm * 128) * lda;
    const __half* Bbase = B + (size_t)(bn * 128) * ldb;

    auto load_stage = [&](int s, int kt) {
        const uint32_t st = sb + (uint32_t)(s * STG_BYTES);
        const int k0 = kt * 16;
#pragma unroll
        for (int i = 0; i < 2; i++) {        // A: 128 rows x 2 chunks = 256
            const int lin = tid + i * 128;
            const int row = lin >> 1, kc = lin & 1;
            cp16(st + swz(row, kc), Abase + (size_t)row * lda + k0 + kc * 8);
        }
#pragma unroll
        for (int i = 0; i < 2; i++) {        // B: 128 rows x 2 chunks = 256
            const int lin = tid + i * 128;
            const int row = lin >> 1, kc = lin & 1;
            cp16(st + A_BYTES + swz(row, kc), Bbase + (size_t)row * ldb + k0 + kc * 8);
        }
        cp_commit();
    };

    // prologue: stages 0..4 in flight
#pragma unroll
    for (int s = 0; s < 5; s++) load_stage(s, s);

    float acc[4][8][4] = {};

    int sl = 5;                              // next stage slot to fill
    for (int kt = 0; kt < nk; kt++) {
        const int rem = nk - 1 - kt;
        if      (rem >= 4) cp_wait<4>();
        else if (rem == 3) cp_wait<3>();
        else if (rem == 2) cp_wait<2>();
        else if (rem == 1) cp_wait<1>();
        else               cp_wait<0>();
        __syncthreads();

        if (kt + 5 < nk) {
            load_stage(sl, kt + 5);
            if (++sl == NSTG) sl = 0;
        }

        const int cs = kt % NSTG;
        const uint32_t st = sb + (uint32_t)(cs * STG_BYTES);

        uint32_t a[4][4], b[8][2];
#pragma unroll
        for (int mt = 0; mt < 4; mt++)
            LDSM4(a[mt][0], a[mt][1], a[mt][2], a[mt][3], st + offA[mt]);
#pragma unroll
        for (int j = 0; j < 4; j++) {
            uint32_t r0, r1, r2, r3;
            LDSM4(r0, r1, r2, r3, st + offB[j]);
            b[2 * j][0] = r0; b[2 * j][1] = r1;
            b[2 * j + 1][0] = r2; b[2 * j + 1][1] = r3;
        }
#pragma unroll
        for (int mt = 0; mt < 4; mt++)
#pragma unroll
            for (int nt = 0; nt < 8; nt++)
                mma_f16(acc[mt][nt], a[mt], b[nt]);
    }

    // ---- epilogue ----
    const int r0 = bm * 128 + wm * 64;
    const int c0 = bn * 128 + wn * 64;
#pragma unroll
    for (int mt = 0; mt < 4; mt++) {
#pragma unroll
        for (int nt = 0; nt < 8; nt++) {
            const int r = r0 + mt * 16 + grp;
            const int c = c0 + nt * 8 + tig * 2;
            float v0 = acc[mt][nt][0] * alpha;
            float v1 = acc[mt][nt][1] * alpha;
            float v2 = acc[mt][nt][2] * alpha;
            float v3 = acc[mt][nt][3] * alpha;
            if (RELU) {
                v0 = fmaxf(v0, 0.f); v1 = fmaxf(v1, 0.f);
                v2 = fmaxf(v2, 0.f); v3 = fmaxf(v3, 0.f);
            }
            if (OUTH) {
                __half* C = (__half*)Cv + zoff * sCz;
                *(__half2*)(C + (size_t)r * ldc + c)       = __floats2half2_rn(v0, v1);
                *(__half2*)(C + (size_t)(r + 8) * ldc + c) = __floats2half2_rn(v2, v3);
            } else {
                float* C = (float*)Cv + zoff * sCz;
                *(float2*)(C + (size_t)r * ldc + c)       = make_float2(v0, v1);
                *(float2*)(C + (size_t)(r + 8) * ldc + c) = make_float2(v2, v3);
            }
        }
    }
}

// ---------------------------------------------------------------------------
// Prep: fp32 -> fp16 for x1 and x2 in one launch (blockIdx.y selects)
// ---------------------------------------------------------------------------
__global__ void __launch_bounds__(256)
f2h_two(const float4* __restrict__ s1, __half2* __restrict__ d1,
        const float4* __restrict__ s2, __half2* __restrict__ d2, int n4)
{
    const int i = blockIdx.x * 256 + threadIdx.x;
    if (i >= n4) return;
    const float4* s = blockIdx.y ? s2 : s1;
    __half2*      d = blockIdx.y ? d2 : d1;
    const float4 v = s[i];
    d[2 * i]     = __floats2half2_rn(v.x, v.y);
    d[2 * i + 1] = __floats2half2_rn(v.z, v.w);
}

// 4 weight transposes (to K-major) + fp16 convert in one launch (blockIdx.z)
__global__ void __launch_bounds__(256)
transpose_h4(const float* __restrict__ w0, const float* __restrict__ w1,
             const float* __restrict__ w2, const float* __restrict__ w3,
             __half* __restrict__ t0, __half* __restrict__ t1,
             __half* __restrict__ t2, __half* __restrict__ t3)
{
    const float* w = (blockIdx.z == 0) ? w0 : (blockIdx.z == 1) ? w1
                   : (blockIdx.z == 2) ? w2 : w3;
    __half* wt     = (blockIdx.z == 0) ? t0 : (blockIdx.z == 1) ? t1
                   : (blockIdx.z == 2) ? t2 : t3;

    __shared__ float t[32][33];
    const int bx = blockIdx.x * 32, by = blockIdx.y * 32;
    const int x = threadIdx.x & 31, y4 = threadIdx.x >> 5;
#pragma unroll
    for (int i = 0; i < 32; i += 8)
        t[y4 + i][x] = w[(size_t)(by + y4 + i) * DD + bx + x];
    __syncthreads();
#pragma unroll
    for (int i = 0; i < 32; i += 8)
        wt[(size_t)(bx + y4 + i) * DD + by + x] = __float2half_rn(t[x][y4 + i]);
}

// ---------------------------------------------------------------------------
// Row softmax with additive mask on fp16 P (compute fp32, store fp16)
// ---------------------------------------------------------------------------
__global__ void __launch_bounds__(256)
softmax_mask(__half* __restrict__ P, const int* __restrict__ mask)
{
    const int row = blockIdx.x;
    const int b   = row >> 11;
    __half* p = P + (size_t)row * SS;
    const int* mrow = mask + (size_t)b * SS;

    const int tid = threadIdx.x, lane = tid & 31, warp = tid >> 5;
    __shared__ float red[8];

    float v[8];
    float mx = -INFINITY;
#pragma unroll
    for (int i = 0; i < 8; i++) {
        const int j = tid + i * 256;
        float x = __half2float(p[j]);
        if (mrow[j]) x -= 1.0e9f;
        v[i] = x;
        mx = fmaxf(mx, x);
    }
#pragma unroll
    for (int o = 16; o; o >>= 1) mx = fmaxf(mx, __shfl_xor_sync(0xffffffffu, mx, o));
    if (lane == 0) red[warp] = mx;
    __syncthreads();
    mx = red[0];
#pragma unroll
    for (int w = 1; w < 8; w++) mx = fmaxf(mx, red[w]);

    float s = 0.f;
#pragma unroll
    for (int i = 0; i < 8; i++) {
        const float e = __expf(v[i] - mx);
        v[i] = e;
        s += e;
    }
    __syncthreads();
#pragma unroll
    for (int o = 16; o; o >>= 1) s += __shfl_xor_sync(0xffffffffu, s, o);
    if (lane == 0) red[warp] = s;
    __syncthreads();
    s = red[0];
#pragma unroll
    for (int w = 1; w < 8; w++) s += red[w];

    const float inv = 1.0f / s;
#pragma unroll
    for (int i = 0; i < 8; i++) p[tid + i * 256] = __float2half_rn(v[i] * inv);
}

// ---------------------------------------------------------------------------
// Launch
// ---------------------------------------------------------------------------
extern "C" void kernel_launch(void* const* d_in, const int* in_sizes, int n_in,
                              void* d_out, int out_size)
{
    (void)in_sizes; (void)n_in; (void)out_size;

    const float* x1      = (const float*)d_in[0];
    const float* x2      = (const float*)d_in[1];
    const int*   maskSeq = (const int*)  d_in[2];
    const float* wq      = (const float*)d_in[3];
    const float* wk      = (const float*)d_in[4];
    const float* wv      = (const float*)d_in[5];
    const float* wo      = (const float*)d_in[6];
    float* out = (float*)d_out;

    __half *x1h, *x2h, *wqT, *wkT, *wvT, *woT, *Q, *Kp, *Vt, *P, *Y;
    cudaGetSymbolAddress((void**)&x1h, g_x1h);
    cudaGetSymbolAddress((void**)&x2h, g_x2h);
    cudaGetSymbolAddress((void**)&wqT, g_wqT);
    cudaGetSymbolAddress((void**)&wkT, g_wkT);
    cudaGetSymbolAddress((void**)&wvT, g_wvT);
    cudaGetSymbolAddress((void**)&woT, g_woT);
    cudaGetSymbolAddress((void**)&Q,   g_Q);
    cudaGetSymbolAddress((void**)&Kp,  g_K);
    cudaGetSymbolAddress((void**)&Vt,  g_Vt);
    cudaGetSymbolAddress((void**)&P,   g_P);
    cudaGetSymbolAddress((void**)&Y,   g_Y);

    cudaFuncSetAttribute(gemm_h<true,  true,  false>, cudaFuncAttributeMaxDynamicSharedMemorySize, SMEM_DYN);
    cudaFuncSetAttribute(gemm_h<false, true,  false>, cudaFuncAttributeMaxDynamicSharedMemorySize, SMEM_DYN);
    cudaFuncSetAttribute(gemm_h<false, true,  true >, cudaFuncAttributeMaxDynamicSharedMemorySize, SMEM_DYN);
    cudaFuncSetAttribute(gemm_h<false, false, false>, cudaFuncAttributeMaxDynamicSharedMemorySize, SMEM_DYN);

    const float scale = 0.03125f;   // 1024^-0.5
    const int n4 = (MTOT * DD) / 4;

    // prep (2 launches)
    f2h_two<<<dim3(n4 / 256, 2), 256>>>((const float4*)x1, (__half2*)x1h,
                                        (const float4*)x2, (__half2*)x2h, n4);
    transpose_h4<<<dim3(32, 32, 4), 256>>>(wq, wk, wv, wo, wqT, wkT, wvT, woT);

    // merged: Q = h(scale * x1 @ wq)  and  K = h(x2 @ wk)
    gemm_h<true, true, false><<<dim3(DD / 128, MTOT / 128, 2), 128, SMEM_DYN>>>(
        x1h, wqT, Q, x2h, wkT, Kp, DD, DD, DD, DD / 16, scale, 1.f, 0, 0, 0);

    // Vt[e, s] = h( sum_d wvT[e,d] * x2h[s,d] )   (V transposed, K-major for PV)
    gemm_h<false, true, false><<<dim3(MTOT / 128, DD / 128, 1), 128, SMEM_DYN>>>(
        wvT, x2h, Vt, wvT, x2h, Vt, DD, DD, MTOT, DD / 16, 1.f, 1.f, 0, 0, 0);

    // P = Q @ K^T  (per batch)
    gemm_h<false, true, false><<<dim3(SS / 128, SS / 128, BB), 128, SMEM_DYN>>>(
        Q, Kp, P, Q, Kp, P, DD, DD, SS, DD / 16, 1.f, 1.f,
        (size_t)SS * DD, (size_t)SS * DD, (size_t)SS * SS);

    // mask + softmax (in place, fp16)
    softmax_mask<<<BB * SS, 256>>>(P, maskSeq);

    // Y = h(relu(P @ Vt^T))  (per batch; Vt batch slice via column offset)
    gemm_h<false, true, true><<<dim3(DD / 128, SS / 128, BB), 128, SMEM_DYN>>>(
        P, Vt, Y, P, Vt, Y, SS, MTOT, DD, SS / 16, 1.f, 1.f,
        (size_t)SS * SS, (size_t)SS, (size_t)SS * DD);

    // out = Y @ wo (fp32 out)
    gemm_h<false, false, false><<<dim3(DD / 128, MTOT / 128, 1), 128, SMEM_DYN>>>(
        Y, woT, out, Y, woT, out, DD, DD, DD, DD / 16, 1.f, 1.f, 0, 0, 0);
}